// round 15
// baseline (speedup 1.0000x reference)
#include <cuda_runtime.h>
#include <cstdint>

// out[b, 0:128]   = emb[idx[b], :]    (128 f32)
// out[b, 128:146] = genre[idx[b], :]  (18 f32)
// idx is int32 (JAX downcasts int64 without x64).
//
// THREE-KERNEL INDEX COMPACTION:
//  K0: zero 512 per-slice cursors.
//  K1: scatter (row,item) into per-slice buckets (slice = item>>8, ~256
//      items = 0.15 MB table footprint each), positions via atomicAdd.
//  K2: gather pass walks buckets slice-major (block id order) -> concurrent
//      CTAs touch only a few slices (~4 MB) -> table gathers hit L2 ~100%,
//      removing the ~115 MB/launch of emb re-reads, at FULL warp density
//      (the thing all full-scan two-pass variants lost).
//  Stores: __stcs float2 to scattered-but-row-contiguous output rows.
//  Determinism: each row stored exactly once; bucket order is irrelevant.
//  Perm entries past count are zero-init/stale valid items (in-bounds
//  gather, store predicated off).

#define NSLICES     512
#define SLICE_SHIFT 8
#define SLICE_CAP   4096   // avg fill ~2560 for B=1M over 391 live slices

__device__ int d_cursor[NSLICES];
__device__ __align__(16) int2 d_perm[NSLICES * SLICE_CAP];   // 16 MB scratch

__global__ void zero_cursor_kernel() {
    d_cursor[threadIdx.x] = 0;                 // launched with NSLICES threads
}

__global__ void __launch_bounds__(256)
scatter_kernel(const int* __restrict__ idx, int B)
{
    int t = blockIdx.x * 256 + threadIdx.x;
    int r = t * 4;
    if (r + 4 <= B) {
        int4 v = __ldcs((const int4*)idx + t);
        int it[4] = {v.x, v.y, v.z, v.w};
        #pragma unroll
        for (int j = 0; j < 4; j++) {
            int s   = it[j] >> SLICE_SHIFT;
            int pos = atomicAdd(&d_cursor[s], 1);
            if (pos < SLICE_CAP)
                d_perm[s * SLICE_CAP + pos] = make_int2(r + j, it[j]);
        }
    } else {
        for (int rr = r; rr < B; rr++) {
            int item = idx[rr];
            int s    = item >> SLICE_SHIFT;
            int pos  = atomicAdd(&d_cursor[s], 1);
            if (pos < SLICE_CAP)
                d_perm[s * SLICE_CAP + pos] = make_int2(rr, item);
        }
    }
}

__global__ void __launch_bounds__(256)
gather_kernel(const float4* __restrict__ emb,   // [N, 32] float4
              const float2* __restrict__ gen,   // [N, 9]  float2
              float2*       __restrict__ out)   // [B, 73] float2
{
    const int lane = threadIdx.x & 31;
    const int w    = threadIdx.x >> 5;
    const int s    = blockIdx.x >> 7;                   // 128 blocks / slice
    const int widx = ((blockIdx.x & 127) << 3) + w;     // warp index in slice
    const int j0   = widx * 4;

    int count = min(d_cursor[s], SLICE_CAP);
    if (j0 >= count) return;
    int n = count - j0;                                  // >= 1

    // 4 bucket entries, broadcast loads (32B aligned: j0 % 4 == 0).
    const int4* p4 = (const int4*)(d_perm + (size_t)s * SLICE_CAP + j0);
    int4 a = __ldg(p4);
    int4 b = __ldg(p4 + 1);
    int rows[4]  = {a.x, a.z, b.x, b.z};
    int items[4] = {a.y, a.w, b.y, b.w};

    // Dense, unconditional gathers (entries past count hold valid items).
    float4 e[4];
    float2 g[4];
    #pragma unroll
    for (int j = 0; j < 4; j++)
        e[j] = __ldg(&emb[(size_t)items[j] * 32 + lane]);
    #pragma unroll
    for (int j = 0; j < 4; j++)
        if (lane < 9)
            g[j] = __ldg(&gen[(size_t)items[j] * 9 + lane]);

    #pragma unroll
    for (int j = 0; j < 4; j++) {
        if (j < n) {
            float2* o = out + (size_t)rows[j] * 73;      // 8B-aligned rows
            __stcs(&o[lane * 2 + 0], make_float2(e[j].x, e[j].y));
            __stcs(&o[lane * 2 + 1], make_float2(e[j].z, e[j].w));
            if (lane < 9)
                __stcs(&o[64 + lane], g[j]);
        }
    }
}

extern "C" void kernel_launch(void* const* d_in, const int* in_sizes, int n_in,
                              void* d_out, int out_size)
{
    const int*    idx = (const int*)   d_in[0];
    const float4* emb = (const float4*)d_in[1];
    const float2* gen = (const float2*)d_in[2];
    float2*       out = (float2*)d_out;

    int B = in_sizes[0];                                   // 1048576

    zero_cursor_kernel<<<1, NSLICES>>>();
    scatter_kernel<<<(B + 1023) / 1024, 256>>>(idx, B);
    gather_kernel<<<NSLICES * (SLICE_CAP / 32), 256>>>(emb, gen, out);
}

// round 16
// speedup vs baseline: 1.2928x; 1.2928x over previous
#include <cuda_runtime.h>
#include <cstdint>

// out[b, 0:128]   = emb[idx[b], :]    (128 f32)
// out[b, 128:146] = genre[idx[b], :]  (18 f32)
// idx is int32 (JAX downcasts int64 without x64).
//
// R5 structure (warp = 4 rows, MLP-first gathers, __stcs float2 stores) with
// emb gathers as 256-bit ld.global.nc.L2::evict_last.v8.b32 (LDG.E.256):
//  - the ONLY ptxas-legal form of the bare evict_last modifier (R6's error
//    message); R7's createpolicy fallback was provably inert, so this is the
//    first real HW test of pinning the 51 MB emb table in L2.
//  - lanes 0..15 cover row 2k (32 B/lane), lanes 16..31 row 2k+1 -> 2 v8
//    loads per warp instead of 4 v4 loads (gather instr count halved).
// Stores: lane half L stores its 32 B as 4 float2 __stcs (row stride 584 B
// is 8B-aligned); genre by lanes 0-8 / 16-24 for their half's row.

#define ROWS_PER_WARP 4

__device__ __forceinline__ void ldg_el_v8(const float* p, float* r) {
    asm volatile(
        "ld.global.nc.L2::evict_last.v8.b32 {%0,%1,%2,%3,%4,%5,%6,%7}, [%8];"
        : "=f"(r[0]), "=f"(r[1]), "=f"(r[2]), "=f"(r[3]),
          "=f"(r[4]), "=f"(r[5]), "=f"(r[6]), "=f"(r[7])
        : "l"(p));
}

__global__ void __launch_bounds__(256)
item_gather_concat_kernel(const int*   __restrict__ idx,
                          const float* __restrict__ emb,   // [N, 128] f32
                          const float2* __restrict__ gen,  // [N, 9]  float2
                          float2*      __restrict__ out,   // [B, 73] float2
                          int B)
{
    const int lane  = threadIdx.x & 31;
    const int half  = lane >> 4;          // 0: rows 2k, 1: rows 2k+1
    const int hl    = lane & 15;          // lane within half-warp
    const int gwarp = (int)((blockIdx.x * (unsigned)blockDim.x + threadIdx.x) >> 5);
    const int r0    = gwarp * ROWS_PER_WARP;

    if (r0 + ROWS_PER_WARP <= B) {
        int4 iv = __ldcs((const int4*)(idx + r0));   // read-once broadcast
        int items[4] = {iv.x, iv.y, iv.z, iv.w};

        // Two v8 gathers cover 4 rows; issue both + genres first (MLP).
        float v[2][8];
        float2 g[2];
        int myitem[2];
        #pragma unroll
        for (int k = 0; k < 2; k++) {
            myitem[k] = items[2 * k + half];
            ldg_el_v8(emb + (size_t)myitem[k] * 128 + hl * 8, v[k]);
        }
        #pragma unroll
        for (int k = 0; k < 2; k++)
            if (hl < 9)
                g[k] = __ldg(&gen[(size_t)myitem[k] * 9 + hl]);

        #pragma unroll
        for (int k = 0; k < 2; k++) {
            int row = r0 + 2 * k + half;
            float2* o = out + (size_t)row * 73;      // 8B-aligned rows
            #pragma unroll
            for (int q = 0; q < 4; q++)
                __stcs(&o[hl * 4 + q], make_float2(v[k][2 * q], v[k][2 * q + 1]));
            if (hl < 9)
                __stcs(&o[64 + hl], g[k]);
        }
    } else {
        // Tail fallback (unused for B = 1M): one row at a time.
        for (int r = r0; r < B && r < r0 + ROWS_PER_WARP; r++) {
            int item = idx[r];
            float4 e = __ldg((const float4*)(emb + (size_t)item * 128) + lane);
            float2* o = out + (size_t)r * 73;
            o[lane * 2 + 0] = make_float2(e.x, e.y);
            o[lane * 2 + 1] = make_float2(e.z, e.w);
            if (lane < 9)
                o[64 + lane] = __ldg(&gen[(size_t)item * 9 + lane]);
        }
    }
}

extern "C" void kernel_launch(void* const* d_in, const int* in_sizes, int n_in,
                              void* d_out, int out_size)
{
    const int*    idx = (const int*)   d_in[0];
    const float*  emb = (const float*) d_in[1];
    const float2* gen = (const float2*)d_in[2];
    float2*       out = (float2*)d_out;

    int B = in_sizes[0];                                   // 1048576
    int rowsPerBlock = 8 * ROWS_PER_WARP;                  // 8 warps/block
    int blocks = (B + rowsPerBlock - 1) / rowsPerBlock;    // 32768

    item_gather_concat_kernel<<<blocks, 256>>>(idx, emb, gen, out, B);
}

// round 17
// speedup vs baseline: 2.1114x; 1.6331x over previous
#include <cuda_runtime.h>
#include <cstdint>

// out[b, 0:128]   = emb[idx[b], :]    (128 f32)
// out[b, 128:146] = genre[idx[b], :]  (18 f32)
// idx is int32 (JAX downcasts int64 without x64).
//
// Warp = 16 rows, staged in 4 sub-groups of 4 (R5's proven MLP-first gather
// pattern, targets smem), then ONE TMA bulk store of the warp's 9344 B:
//   - 16*584 = 9344 = 73*128 -> every warp's output region is 128B-LINE-
//     ALIGNED: zero partial-line edges, zero L2 RMW fills (R14's +80 MB bug)
//   - async proxy writes at R14's measured 6.4 TB/s ceiling, no STG
//     wavefronts through L1, no block barrier (warp-private staging)
//   - one wait_group per 16 rows (4x better amortized than R14)
// Block = 128 threads (4 warps): 37376 B static smem, 6 blocks/SM.

#define ROWS_PER_WARP 16
#define WARP_FLOATS   (ROWS_PER_WARP * 146)    // 2336 floats = 9344 B
#define WARP_BYTES    (WARP_FLOATS * 4)
#define WARPS_PER_BLK 4

__global__ void __launch_bounds__(128)
item_gather_concat_kernel(const int*    __restrict__ idx,
                          const float4* __restrict__ emb,   // [N, 32] float4
                          const float2* __restrict__ gen,   // [N, 9]  float2
                          float*        __restrict__ out,   // [B*146] floats
                          int B)
{
    __shared__ __align__(128) float s[WARPS_PER_BLK * WARP_FLOATS];  // 37376 B

    const int lane  = threadIdx.x & 31;
    const int w     = threadIdx.x >> 5;
    const int gwarp = (int)((blockIdx.x * (unsigned)blockDim.x + threadIdx.x) >> 5);
    const int r0    = gwarp * ROWS_PER_WARP;

    float* sw = s + w * WARP_FLOATS;

    if (r0 + ROWS_PER_WARP <= B) {
        // ---- 4 sub-groups of 4 rows: gather (MLP-first) -> stage ----
        #pragma unroll
        for (int gq = 0; gq < 4; gq++) {
            int4 iv = __ldcs((const int4*)(idx + r0 + gq * 4));
            int items[4] = {iv.x, iv.y, iv.z, iv.w};

            float4 e[4];
            float2 g[4];
            #pragma unroll
            for (int j = 0; j < 4; j++)
                e[j] = __ldg(&emb[(size_t)items[j] * 32 + lane]);
            #pragma unroll
            for (int j = 0; j < 4; j++)
                if (lane < 9)
                    g[j] = __ldg(&gen[(size_t)items[j] * 9 + lane]);

            #pragma unroll
            for (int j = 0; j < 4; j++) {
                float* srow = sw + (gq * 4 + j) * 146;
                *(float2*)(srow + lane * 4)     = make_float2(e[j].x, e[j].y);
                *(float2*)(srow + lane * 4 + 2) = make_float2(e[j].z, e[j].w);
                if (lane < 9)
                    *(float2*)(srow + 128 + lane * 2) = g[j];
            }
        }

        // ---- one line-aligned TMA bulk store of the warp's 9344 B ----
        asm volatile("fence.proxy.async.shared::cta;" ::: "memory");
        __syncwarp();
        if (lane == 0) {
            float* gdst = out + (size_t)gwarp * WARP_FLOATS;   // 9344B-aligned
            unsigned ssrc = (unsigned)__cvta_generic_to_shared(sw);
            asm volatile(
                "cp.async.bulk.global.shared::cta.bulk_group [%0], [%1], %2;"
                :: "l"(gdst), "r"(ssrc), "r"(WARP_BYTES) : "memory");
            asm volatile("cp.async.bulk.commit_group;" ::: "memory");
            asm volatile("cp.async.bulk.wait_group 0;" ::: "memory");
        }
    } else {
        // Tail fallback (unused for B = 1M): one row at a time.
        for (int r = r0; r < B && r < r0 + ROWS_PER_WARP; r++) {
            int item = idx[r];
            float4 e = __ldg(&emb[(size_t)item * 32 + lane]);
            float2* o = (float2*)(out + (size_t)r * 146);
            o[lane * 2 + 0] = make_float2(e.x, e.y);
            o[lane * 2 + 1] = make_float2(e.z, e.w);
            if (lane < 9)
                o[64 + lane] = __ldg(&gen[(size_t)item * 9 + lane]);
        }
    }
}

extern "C" void kernel_launch(void* const* d_in, const int* in_sizes, int n_in,
                              void* d_out, int out_size)
{
    const int*    idx = (const int*)   d_in[0];
    const float4* emb = (const float4*)d_in[1];
    const float2* gen = (const float2*)d_in[2];
    float*        out = (float*)d_out;

    int B = in_sizes[0];                                     // 1048576
    int rowsPerBlock = WARPS_PER_BLK * ROWS_PER_WARP;        // 64 rows/block
    int blocks = (B + rowsPerBlock - 1) / rowsPerBlock;      // 16384

    item_gather_concat_kernel<<<blocks, 128>>>(idx, emb, gen, out, B);
}